// round 15
// baseline (speedup 1.0000x reference)
#include <cuda_runtime.h>
#include <cuda_bf16.h>
#include <math.h>

// ---------------------------------------------------------------------------
// Problem constants
// ---------------------------------------------------------------------------
#define BATCH 4
#define IMG_H 512
#define IMG_W 512
#define PATCH 64
#define STRIDE_ 32
#define NPATCH 256
#define PATCHES_ELEMS (BATCH * NPATCH * 3 * PATCH * PATCH)   // 12,582,912
#define FLOW_ELEMS    (BATCH * 2 * IMG_H * IMG_W)            //  2,097,152

// Scratch (device globals). Activation = interleaved hi/lo, 32 bf16 per pixel.
__device__ __align__(256) float g_bufA[33554432];
__device__ __align__(256) float g_bufB[33554432];

// Packed weights: per (layer, cb, tap, ct): [32 lanes x 16B hi][32 lanes x 16B lo]
#define WSCRATCH2 276480
__device__ __align__(256) __nv_bfloat16 g_wpk[WSCRATCH2];

// ---------------------------------------------------------------------------
// helpers
// ---------------------------------------------------------------------------
__device__ __forceinline__ unsigned su32(const void* p) {
    return (unsigned)__cvta_generic_to_shared(p);
}
__device__ __forceinline__ void cp_async16(void* smem_dst, const void* gptr) {
    asm volatile("cp.async.cg.shared.global [%0], [%1], 16;"
                 :: "r"(su32(smem_dst)), "l"(gptr));
}
__device__ __forceinline__ void cp_commit() { asm volatile("cp.async.commit_group;"); }
__device__ __forceinline__ void cp_wait0()  { asm volatile("cp.async.wait_group 0;"); }

__device__ __forceinline__ void cp_bulk(unsigned sdst, const void* g, unsigned bytes,
                                        unsigned mbar) {
    asm volatile(
        "cp.async.bulk.shared::cta.global.mbarrier::complete_tx::bytes [%0], [%1], %2, [%3];"
        :: "r"(sdst), "l"(g), "r"(bytes), "r"(mbar) : "memory");
}
__device__ __forceinline__ void mbar_init(unsigned addr, unsigned cnt) {
    asm volatile("mbarrier.init.shared.b64 [%0], %1;" :: "r"(addr), "r"(cnt) : "memory");
}
__device__ __forceinline__ void mbar_expect_tx(unsigned addr, unsigned bytes) {
    asm volatile("mbarrier.arrive.expect_tx.shared.b64 _, [%0], %1;"
                 :: "r"(addr), "r"(bytes) : "memory");
}
__device__ __forceinline__ void mbar_wait(unsigned addr, unsigned parity) {
    asm volatile(
        "{\n\t.reg .pred P;\n\t"
        "W_%=:\n\t"
        "mbarrier.try_wait.parity.acquire.cta.shared::cta.b64 P, [%0], %1, 0x989680;\n\t"
        "@P bra.uni D_%=;\n\t"
        "bra.uni W_%=;\n\t"
        "D_%=:\n\t}"
        :: "r"(addr), "r"(parity) : "memory");
}

__device__ __forceinline__ void mma16816(float* c, const unsigned* a, unsigned b0, unsigned b1) {
    asm volatile(
        "mma.sync.aligned.m16n8k16.row.col.f32.bf16.bf16.f32 "
        "{%0,%1,%2,%3}, {%4,%5,%6,%7}, {%8,%9}, {%0,%1,%2,%3};"
        : "+f"(c[0]), "+f"(c[1]), "+f"(c[2]), "+f"(c[3])
        : "r"(a[0]), "r"(a[1]), "r"(a[2]), "r"(a[3]), "r"(b0), "r"(b1));
}

// slot permutation within 16 channels
__device__ __forceinline__ int pos16(int ci) {
    return (((ci >> 1) & 3) << 2) + (((ci >> 3) & 1) << 1) + (ci & 1);
}
// interleaved layout: hi offset = 8*(s>>2)+(s&3), lo = +4
__device__ __forceinline__ int hoff16(int s) { return 8 * (s >> 2) + (s & 3); }

__device__ __forceinline__ void bf16split(float v, __nv_bfloat16& h, __nv_bfloat16& l) {
    h = __float2bfloat16(v);
    l = __float2bfloat16(v - __bfloat162float(h));
}

// ---------------------------------------------------------------------------
// Fused weight preconversion: fp32 -> packed per-lane mma A-fragments.
// ---------------------------------------------------------------------------
__constant__ int c_woffs2[9] = {0, 9216, 27648, 64512, 138240, 211968, 248832, 267264, 276480};
__constant__ int c_wCOUT[8]  = {32, 32, 64, 64, 64, 32, 32, 2};
__constant__ int c_wCIN[8]   = {3, 32, 32, 64, 64, 64, 32, 32};
__constant__ int c_wNCT[8]   = {2, 2, 4, 4, 4, 2, 2, 1};

__global__ void wconv_all(const float* __restrict__ w0, const float* __restrict__ w1,
                          const float* __restrict__ w2, const float* __restrict__ w3,
                          const float* __restrict__ w4, const float* __restrict__ w5,
                          const float* __restrict__ w6, const float* __restrict__ w7,
                          __nv_bfloat16* __restrict__ dst)
{
    int idx = blockIdx.x * blockDim.x + threadIdx.x;
    if (idx >= WSCRATCH2) return;
    int l = 0;
    while (idx >= c_woffs2[l + 1]) l++;
    int rel = idx - c_woffs2[l];
    int COUT = c_wCOUT[l], CIN = c_wCIN[l], NCT = c_wNCT[l];
    int e    = rel & 255;
    int plane = (rel >> 8) & 1;
    int unit = rel >> 9;
    int ct  = unit % NCT;  unit /= NCT;
    int tap = unit % 9;
    int cb  = unit / 9;
    int lane = e >> 3;
    int e8 = e & 7;
    int j = e8 >> 1, kk = e8 & 1;
    int gid = lane >> 2, q = lane & 3;
    int co = ct * 16 + gid + (j & 1) * 8;
    int k  = 2 * q + kk + ((j & 2) ? 8 : 0);
    int ci_g = cb * 16 + k;
    const float* w;
    switch (l) {
        case 0: w = w0; break; case 1: w = w1; break;
        case 2: w = w2; break; case 3: w = w3; break;
        case 4: w = w4; break; case 5: w = w5; break;
        case 6: w = w6; break; default: w = w7; break;
    }
    float v = 0.f;
    if (co < COUT && ci_g < CIN)
        v = w[((size_t)co * CIN + ci_g) * 9 + tap];
    __nv_bfloat16 h = __float2bfloat16(v);
    dst[idx] = plane ? __float2bfloat16(v - __bfloat162float(h)) : h;
}

// ---------------------------------------------------------------------------
// Implicit-GEMM 3x3 conv via mma.sync bf16 (3-term hi/lo split), layout v2.
// Tile: (NT*8) wide x 8 tall x (NCT*16) couts. 256 threads (8 warps).
// Double-buffered input staging via cp.async.bulk + 3 mbarriers (INX=0);
// direct fp32->bf16 conversion from x (INX=1, conv0 only).
// OUTMODE: 0 = act layout (+relu), smem-staged vectorized epilogue
//          1 = fp32 NCHW (+tanh)
//          2 = act layout, fused bias+relu+MaxPool2x2, vectorized store
// ---------------------------------------------------------------------------
template <int NCT, int NT, int OUTMODE, int INX>
__global__ void __launch_bounds__(256, 2)
conv_mma_kernel(const __nv_bfloat16* __restrict__ gact,
                const float* __restrict__ xin,
                const __nv_bfloat16* __restrict__ gw,
                const float* __restrict__ bias,
                __nv_bfloat16* __restrict__ oact,
                float* __restrict__ of32,
                int H, int W, int CBIN, int COUT)
{
    constexpr int COUTP = NCT * 16;
    constexpr int TILEW = NT * 8;
    constexpr int PITCH = TILEW + 4;
    constexpr int INP = 10 * PITCH * 32;      // bf16 per input buffer
    constexpr int WPL = 9 * NCT * 512;        // bf16 per weight chunk
    extern __shared__ char smraw[];
    __nv_bfloat16* s_in0 = (__nv_bfloat16*)smraw;
    __nv_bfloat16* s_in1 = s_in0 + INP;
    __nv_bfloat16* s_w   = s_in0 + 2 * INP;
    const unsigned mb_base = su32(smraw) + (2 * INP + WPL) * 2;
    const unsigned mb_in0 = mb_base, mb_in1 = mb_base + 8, mb_w = mb_base + 16;

    const int bx = blockIdx.x * TILEW;
    const int by = blockIdx.y * 8;
    const int b  = blockIdx.z;

    const int tid  = threadIdx.x;
    const int warp = tid >> 5;
    const int lane = tid & 31;
    const int gid  = lane >> 2;
    const int qid  = lane & 3;

    float acc[NCT][NT][4];
#pragma unroll
    for (int ct = 0; ct < NCT; ct++)
#pragma unroll
        for (int nt = 0; nt < NT; nt++) {
            acc[ct][nt][0] = 0.f; acc[ct][nt][1] = 0.f;
            acc[ct][nt][2] = 0.f; acc[ct][nt][3] = 0.f;
        }

    // halo geometry (static per CTA)
    const int r0 = (by == 0) ? 1 : 0;
    const int r1 = (by + 8 >= H) ? 9 : 10;
    const int c0 = (bx == 0) ? 1 : 0;
    const int c1 = (bx + TILEW >= W) ? (TILEW + 1) : (TILEW + 2);
    const unsigned rowBytes = (unsigned)(c1 - c0) * 64u;
    const unsigned inBytes  = (unsigned)(r1 - r0) * rowBytes;

    if (!INX) {
        if (tid == 0) {
            mbar_init(mb_in0, 1);
            mbar_init(mb_in1, 1);
            mbar_init(mb_w, 1);
        }
        // zero-fill OOB halo ONCE in BOTH buffers
        for (int p = tid; p < 10 * (TILEW + 2); p += 256) {
            int row = p / (TILEW + 2);
            int col = p - row * (TILEW + 2);
            if (row < r0 || row >= r1 || col < c0 || col >= c1) {
                uint4 z = make_uint4(0u, 0u, 0u, 0u);
                uint4* d0 = (uint4*)(s_in0 + (row * PITCH + col) * 32);
                uint4* d1 = (uint4*)(s_in1 + (row * PITCH + col) * 32);
                d0[0] = z; d0[1] = z; d0[2] = z; d0[3] = z;
                d1[0] = z; d1[1] = z; d1[2] = z; d1[3] = z;
            }
        }
        __syncthreads();   // init + zero-fill visible before staging/waits
        if (tid == 0) {
            // prologue: input chunk 0 + weights chunk 0
            mbar_expect_tx(mb_in0, inBytes);
            for (int r = r0; r < r1; r++) {
                int gy = by + r - 1;
                const __nv_bfloat16* src = gact +
                    ((((size_t)b * CBIN + 0) * H + gy) * W + (bx + c0 - 1)) * 32;
                cp_bulk(su32(s_in0 + (r * PITCH + c0) * 32), src, rowBytes, mb_in0);
            }
            mbar_expect_tx(mb_w, (unsigned)WPL * 2u);
            cp_bulk(su32(s_w), gw, (unsigned)WPL * 2u, mb_w);
        }
    }

    int ph_in0 = 0, ph_in1 = 0, ph_w = 0;

    for (int cb = 0; cb < CBIN; cb++) {
        const int buf = cb & 1;
        if (INX) {
            __syncthreads();
            for (int idx = tid * 8; idx < WPL; idx += 2048)
                cp_async16(s_w + idx, gw + idx);
            for (int p = tid; p < 10 * (TILEW + 2); p += 256) {
                int row = p / (TILEW + 2);
                int col = p - row * (TILEW + 2);
                int gy = by + row - 1;
                int gx = bx + col - 1;
                __nv_bfloat16 arr[32];
#pragma unroll
                for (int i = 0; i < 32; i++) arr[i] = __float2bfloat16(0.f);
                if (gy >= 0 && gy < H && gx >= 0 && gx < W) {
#pragma unroll
                    for (int ci = 0; ci < 3; ci++) {
                        float v = xin[((size_t)(b * 3 + ci) * H + gy) * W + gx];
                        __nv_bfloat16 h, l;
                        bf16split(v, h, l);
                        int hf = hoff16(pos16(ci));
                        arr[hf] = h;
                        arr[hf + 4] = l;
                    }
                }
                uint4* src = (uint4*)arr;
                uint4* dst = (uint4*)(s_in0 + (row * PITCH + col) * 32);
                dst[0] = src[0]; dst[1] = src[1]; dst[2] = src[2]; dst[3] = src[3];
            }
            cp_commit();
            cp_wait0();
            __syncthreads();
        } else {
            // issue input prefetch for chunk cb+1 into the other buffer
            if (tid == 0 && cb + 1 < CBIN) {
                unsigned mb_n = buf ? mb_in0 : mb_in1;
                __nv_bfloat16* s_n = buf ? s_in0 : s_in1;
                mbar_expect_tx(mb_n, inBytes);
                for (int r = r0; r < r1; r++) {
                    int gy = by + r - 1;
                    const __nv_bfloat16* src = gact +
                        ((((size_t)b * CBIN + (cb + 1)) * H + gy) * W + (bx + c0 - 1)) * 32;
                    cp_bulk(su32(s_n + (r * PITCH + c0) * 32), src, rowBytes, mb_n);
                }
            }
            // wait current input + weights
            if (buf == 0) { mbar_wait(mb_in0, (unsigned)ph_in0); ph_in0 ^= 1; }
            else          { mbar_wait(mb_in1, (unsigned)ph_in1); ph_in1 ^= 1; }
            mbar_wait(mb_w, (unsigned)ph_w); ph_w ^= 1;
        }

        const __nv_bfloat16* s_act = buf ? s_in1 : s_in0;

        // ---- compute: 9 taps ----
        int ky = 0, kx = 0;
#pragma unroll 1
        for (int tap = 0; tap < 9; tap++) {
            unsigned ah[NCT][4], al[NCT][4];
            const int wb = tap * NCT * 512 + lane * 8;
#pragma unroll
            for (int ct = 0; ct < NCT; ct++) {
                uint4 hv = *(const uint4*)(s_w + wb + ct * 512);
                uint4 lv = *(const uint4*)(s_w + wb + ct * 512 + 256);
                ah[ct][0] = hv.x; ah[ct][1] = hv.y; ah[ct][2] = hv.z; ah[ct][3] = hv.w;
                al[ct][0] = lv.x; al[ct][1] = lv.y; al[ct][2] = lv.z; al[ct][3] = lv.w;
            }
            const int rowb = warp + ky;
#pragma unroll
            for (int nt = 0; nt < NT; nt++) {
                int colb = nt * 8 + gid + kx;
                uint4 bv = *(const uint4*)(s_act + (rowb * PITCH + colb) * 32 + 8 * qid);
#pragma unroll
                for (int ct = 0; ct < NCT; ct++) {
                    mma16816(acc[ct][nt], ah[ct], bv.x, bv.y);
                    mma16816(acc[ct][nt], ah[ct], bv.z, bv.w);
                    mma16816(acc[ct][nt], al[ct], bv.x, bv.y);
                }
            }
            if (++kx == 3) { kx = 0; ++ky; }
        }

        if (!INX && cb + 1 < CBIN) {
            __syncthreads();   // all warps done with s_w before overwrite
            if (tid == 0) {
                mbar_expect_tx(mb_w, (unsigned)WPL * 2u);
                cp_bulk(su32(s_w), gw + (size_t)(cb + 1) * WPL, (unsigned)WPL * 2u, mb_w);
            }
        }
    }

    // ---- epilogue ----
    const int gy = by + warp;
    const int s0 = 4 * (gid >> 1) + (gid & 1);   // pos16(gid)
    const int s1 = s0 + 2;                       // pos16(gid + 8)
    if (OUTMODE == 1) {
#pragma unroll
        for (int ct = 0; ct < NCT; ct++) {
            int co0r = ct * 16 + gid;
            int co1r = co0r + 8;
            bool ok0 = co0r < COUT;
            bool ok1 = co1r < COUT;
            float bv0 = ok0 ? bias[co0r] : 0.f;
            float bv1 = ok1 ? bias[co1r] : 0.f;
#pragma unroll
            for (int nt = 0; nt < NT; nt++) {
                int gxv = bx + nt * 8 + 2 * qid;
                if (ok0) {
                    float v0 = tanhf(acc[ct][nt][0] + bv0);
                    float v1 = tanhf(acc[ct][nt][1] + bv0);
                    *(float2*)&of32[((size_t)(b * COUT + co0r) * H + gy) * W + gxv]
                        = make_float2(v0, v1);
                }
                if (ok1) {
                    float v0 = tanhf(acc[ct][nt][2] + bv1);
                    float v1 = tanhf(acc[ct][nt][3] + bv1);
                    *(float2*)&of32[((size_t)(b * COUT + co1r) * H + gy) * W + gxv]
                        = make_float2(v0, v1);
                }
            }
        }
    } else if (OUTMODE == 0) {
        // stage fp32 results in smem (slot-ordered channels), then emit
        // fully-vectorized 16B stores.
        constexpr int PC0 = COUTP + 1;
        float* s_pool = (float*)smraw;
        __syncthreads();
#pragma unroll
        for (int ct = 0; ct < NCT; ct++) {
            float bv0 = bias[ct * 16 + gid];
            float bv1 = bias[ct * 16 + 8 + gid];
#pragma unroll
            for (int nt = 0; nt < NT; nt++) {
                int col = nt * 8 + 2 * qid;
                int px = warp * TILEW + col;
                s_pool[px * PC0 + ct * 16 + s0]       = fmaxf(acc[ct][nt][0] + bv0, 0.f);
                s_pool[(px + 1) * PC0 + ct * 16 + s0] = fmaxf(acc[ct][nt][1] + bv0, 0.f);
                s_pool[px * PC0 + ct * 16 + s1]       = fmaxf(acc[ct][nt][2] + bv1, 0.f);
                s_pool[(px + 1) * PC0 + ct * 16 + s1] = fmaxf(acc[ct][nt][3] + bv1, 0.f);
            }
        }
        __syncthreads();
        const int nCB = COUTP >> 4;          // == COUT >> 4 for these layers
        const int TOT = 8 * TILEW * nCB;
        for (int v = tid; v < TOT; v += 256) {
            int cg = v & (nCB - 1);
            int px = v / nCB;
            int gy2 = by + px / TILEW;
            int gx2 = bx + (px % TILEW);
            const float* f = s_pool + px * PC0 + cg * 16;
            __nv_bfloat16 arr[32];
#pragma unroll
            for (int g = 0; g < 4; g++)
#pragma unroll
                for (int k = 0; k < 4; k++) {
                    __nv_bfloat16 h, l;
                    bf16split(f[4 * g + k], h, l);
                    arr[8 * g + k] = h;
                    arr[8 * g + 4 + k] = l;
                }
            uint4* dst = (uint4*)(oact +
                ((((size_t)b * nCB + cg) * H + gy2) * W + gx2) * 32);
#pragma unroll
            for (int i = 0; i < 4; i++) dst[i] = ((uint4*)arr)[i];
        }
    } else {
        // OUTMODE 2: fused bias + relu + MaxPool 2x2, vectorized store
        constexpr int PW = NT * 4;
        constexpr int PC = COUTP + 1;
        float* s_pool = (float*)smraw;
        __syncthreads();
#pragma unroll
        for (int ct = 0; ct < NCT; ct++) {
            float bv0 = bias[ct * 16 + gid];
            float bv1 = bias[ct * 16 + 8 + gid];
#pragma unroll
            for (int nt = 0; nt < NT; nt++) {
                float v0 = fmaxf(acc[ct][nt][0] + bv0, 0.f);
                float v1 = fmaxf(acc[ct][nt][1] + bv0, 0.f);
                float v2 = fmaxf(acc[ct][nt][2] + bv1, 0.f);
                float v3 = fmaxf(acc[ct][nt][3] + bv1, 0.f);
                int px = nt * 4 + qid;
                s_pool[(warp * PW + px) * PC + ct * 16 + s0] = fmaxf(v0, v1);
                s_pool[(warp * PW + px) * PC + ct * 16 + s1] = fmaxf(v2, v3);
            }
        }
        __syncthreads();
        const int H2 = H >> 1, W2 = W >> 1;
        const int nCB = COUTP >> 4;
        const int TOT = 4 * PW * nCB;
        for (int v = tid; v < TOT; v += 256) {
            int cg = v & (nCB - 1);
            int r = v / nCB;
            int px = r % PW;
            int prow = r / PW;
            const float* fa = s_pool + ((2 * prow) * PW + px) * PC + cg * 16;
            const float* fb = s_pool + ((2 * prow + 1) * PW + px) * PC + cg * 16;
            __nv_bfloat16 arr[32];
#pragma unroll
            for (int g = 0; g < 4; g++)
#pragma unroll
                for (int k = 0; k < 4; k++) {
                    float m = fmaxf(fa[4 * g + k], fb[4 * g + k]);
                    __nv_bfloat16 h, l;
                    bf16split(m, h, l);
                    arr[8 * g + k] = h;
                    arr[8 * g + 4 + k] = l;
                }
            int gy2 = (by >> 1) + prow;
            int gx2 = (bx >> 1) + px;
            uint4* dst = (uint4*)(oact +
                ((((size_t)b * nCB + cg) * H2 + gy2) * W2 + gx2) * 32);
#pragma unroll
            for (int i = 0; i < 4; i++) dst[i] = ((uint4*)arr)[i];
        }
    }
}

// ---------------------------------------------------------------------------
// Bilinear upsample x2, vectorized: 1 thread per output pixel (32 bf16).
// ---------------------------------------------------------------------------
__global__ void up_bf16_v2(const __nv_bfloat16* __restrict__ iact,
                           __nv_bfloat16* __restrict__ oact,
                           int total, int Hin, int Win)
{
    int p = blockIdx.x * blockDim.x + threadIdx.x;
    if (p >= total) return;
    int Hout = 2 * Hin, Wout = 2 * Win;
    int ox = p % Wout;
    int t = p / Wout;
    int oy = t % Hout;
    int c = t / Hout;

    float fy = (oy + 0.5f) * 0.5f - 0.5f;
    float fx = (ox + 0.5f) * 0.5f - 0.5f;
    int y0 = (int)floorf(fy);
    int x0 = (int)floorf(fx);
    float wy = fy - (float)y0;
    float wx = fx - (float)x0;
    int y0c = max(y0, 0), y1c = min(y0 + 1, Hin - 1);
    int x0c = max(x0, 0), x1c = min(x0 + 1, Win - 1);
    float w00 = (1.f - wy) * (1.f - wx), w01 = (1.f - wy) * wx;
    float w10 = wy * (1.f - wx),         w11 = wy * wx;

    size_t cb = (size_t)c * Hin;
    const uint4* p00 = (const uint4*)(iact + ((cb + y0c) * Win + x0c) * 32);
    const uint4* p01 = (const uint4*)(iact + ((cb + y0c) * Win + x1c) * 32);
    const uint4* p10 = (const uint4*)(iact + ((cb + y1c) * Win + x0c) * 32);
    const uint4* p11 = (const uint4*)(iact + ((cb + y1c) * Win + x1c) * 32);

    __nv_bfloat16 a00[32], a01[32], a10[32], a11[32], o[32];
#pragma unroll
    for (int i = 0; i < 4; i++) {
        ((uint4*)a00)[i] = p00[i];
        ((uint4*)a01)[i] = p01[i];
        ((uint4*)a10)[i] = p10[i];
        ((uint4*)a11)[i] = p11[i];
    }
#pragma unroll
    for (int g = 0; g < 4; g++) {
#pragma unroll
        for (int k = 0; k < 4; k++) {
            int hi = 8 * g + k, lo = hi + 4;
            float v00 = __bfloat162float(a00[hi]) + __bfloat162float(a00[lo]);
            float v01 = __bfloat162float(a01[hi]) + __bfloat162float(a01[lo]);
            float v10 = __bfloat162float(a10[hi]) + __bfloat162float(a10[lo]);
            float v11 = __bfloat162float(a11[hi]) + __bfloat162float(a11[lo]);
            float v = w00 * v00 + w01 * v01 + w10 * v10 + w11 * v11;
            __nv_bfloat16 h, l;
            bf16split(v, h, l);
            o[hi] = h;
            o[lo] = l;
        }
    }
    uint4* dst = (uint4*)(oact + (size_t)p * 32);
#pragma unroll
    for (int i = 0; i < 4; i++) dst[i] = ((uint4*)o)[i];
}

// ---------------------------------------------------------------------------
// deformed = base_grid + flow^T * temp
// ---------------------------------------------------------------------------
__global__ void deform_kernel(const float* __restrict__ flow,
                              const float* __restrict__ temp,
                              float* __restrict__ def)
{
    int idx = blockIdx.x * blockDim.x + threadIdx.x;
    int total = BATCH * IMG_H * IMG_W;
    if (idx >= total) return;
    int w = idx % IMG_W;
    int h = (idx / IMG_W) % IMG_H;
    int b = idx / (IMG_W * IMG_H);
    float gx = -1.0f + 2.0f * (float)w / (float)(IMG_W - 1);
    float gy = -1.0f + 2.0f * (float)h / (float)(IMG_H - 1);
    float t = temp[0];
    float fx = flow[((size_t)(b * 2 + 0) * IMG_H + h) * IMG_W + w];
    float fy = flow[((size_t)(b * 2 + 1) * IMG_H + h) * IMG_W + w];
    def[(size_t)idx * 2 + 0] = gx + fx * t;
    def[(size_t)idx * 2 + 1] = gy + fy * t;
}

// ---------------------------------------------------------------------------
// Patch extraction (grid_sample bilinear, zeros padding)
// ---------------------------------------------------------------------------
__global__ void patches_kernel(const float* __restrict__ x,
                               const float* __restrict__ def,
                               float* __restrict__ out)
{
    int bn = blockIdx.x;
    int b = bn >> 8;
    int n = bn & 255;
    int hy = n >> 4;
    int wx = n & 15;
    const float* dptr = def + (((size_t)(b * IMG_H + hy * STRIDE_) * IMG_W) + wx * STRIDE_) * 2;
    float cx = dptr[0];
    float cy = dptr[1];

    for (int p = threadIdx.x; p < PATCH * PATCH; p += blockDim.x) {
        int i = p >> 6;
        int j = p & 63;
        float pxv = -1.0f + 2.0f * (float)j / (float)(PATCH - 1);
        float pyv = -1.0f + 2.0f * (float)i / (float)(PATCH - 1);
        float gx = cx + pxv * ((float)PATCH / (float)IMG_W);
        float gy = cy + pyv * ((float)PATCH / (float)IMG_H);
        float ix = ((gx + 1.0f) * (float)IMG_W - 1.0f) * 0.5f;
        float iy = ((gy + 1.0f) * (float)IMG_H - 1.0f) * 0.5f;
        float x0f = floorf(ix), y0f = floorf(iy);
        float wx1 = ix - x0f, wy1 = iy - y0f;
        int x0 = (int)x0f, y0 = (int)y0f;
        int x1 = x0 + 1, y1 = y0 + 1;
        bool vx0 = (x0 >= 0) & (x0 <= IMG_W - 1);
        bool vx1 = (x1 >= 0) & (x1 <= IMG_W - 1);
        bool vy0 = (y0 >= 0) & (y0 <= IMG_H - 1);
        bool vy1 = (y1 >= 0) & (y1 <= IMG_H - 1);
        int x0c = min(max(x0, 0), IMG_W - 1);
        int x1c = min(max(x1, 0), IMG_W - 1);
        int y0c = min(max(y0, 0), IMG_H - 1);
        int y1c = min(max(y1, 0), IMG_H - 1);
        float w00 = (1.f - wx1) * (1.f - wy1) * (float)(vx0 && vy0);
        float w10 = wx1 * (1.f - wy1) * (float)(vx1 && vy0);
        float w01 = (1.f - wx1) * wy1 * (float)(vx0 && vy1);
        float w11 = wx1 * wy1 * (float)(vx1 && vy1);

#pragma unroll
        for (int c = 0; c < 3; c++) {
            const float* img = x + (size_t)(b * 3 + c) * IMG_H * IMG_W;
            float v = img[y0c * IMG_W + x0c] * w00
                    + img[y0c * IMG_W + x1c] * w10
                    + img[y1c * IMG_W + x0c] * w01
                    + img[y1c * IMG_W + x1c] * w11;
            out[((size_t)(bn)*3 + c) * (PATCH * PATCH) + p] = v;
        }
    }
}

// ---------------------------------------------------------------------------
// Launch
// ---------------------------------------------------------------------------
#define SMEM_C2_8 ((2 * 10 * 68 * 32 + 9 * 2 * 512) * 2 + 32)   // 105,504 B
#define SMEM_C4_4 ((2 * 10 * 36 * 32 + 9 * 4 * 512) * 2 + 32)   //  82,976 B
#define SMEM_C1_8 ((2 * 10 * 68 * 32 + 9 * 1 * 512) * 2 + 32)   //  96,288 B

extern "C" void kernel_launch(void* const* d_in, const int* in_sizes, int n_in,
                              void* d_out, int out_size)
{
    const float* x  = (const float*)d_in[0];
    const float* w0 = (const float*)d_in[1];  const float* b0 = (const float*)d_in[2];
    const float* w1 = (const float*)d_in[3];  const float* b1 = (const float*)d_in[4];
    const float* w2 = (const float*)d_in[5];  const float* b2 = (const float*)d_in[6];
    const float* w3 = (const float*)d_in[7];  const float* b3 = (const float*)d_in[8];
    const float* w4 = (const float*)d_in[9];  const float* b4 = (const float*)d_in[10];
    const float* w5 = (const float*)d_in[11]; const float* b5 = (const float*)d_in[12];
    const float* w6 = (const float*)d_in[13]; const float* b6 = (const float*)d_in[14];
    const float* w7 = (const float*)d_in[15]; const float* b7 = (const float*)d_in[16];
    const float* temp = (const float*)d_in[17];

    float* out     = (float*)d_out;
    float* patches = out;
    float* flow    = out + PATCHES_ELEMS;
    float* def     = out + PATCHES_ELEMS + FLOW_ELEMS;

    float* A;  cudaGetSymbolAddress((void**)&A, g_bufA);
    float* Bb; cudaGetSymbolAddress((void**)&Bb, g_bufB);
    __nv_bfloat16* WP; cudaGetSymbolAddress((void**)&WP, g_wpk);

    __nv_bfloat16* Apk = (__nv_bfloat16*)A;
    __nv_bfloat16* Bpk = (__nv_bfloat16*)Bb;

    cudaFuncSetAttribute((const void*)conv_mma_kernel<2, 8, 0, 1>,
                         cudaFuncAttributeMaxDynamicSharedMemorySize, SMEM_C2_8);
    cudaFuncSetAttribute((const void*)conv_mma_kernel<2, 8, 0, 0>,
                         cudaFuncAttributeMaxDynamicSharedMemorySize, SMEM_C2_8);
    cudaFuncSetAttribute((const void*)conv_mma_kernel<2, 8, 2, 0>,
                         cudaFuncAttributeMaxDynamicSharedMemorySize, SMEM_C2_8);
    cudaFuncSetAttribute((const void*)conv_mma_kernel<4, 4, 0, 0>,
                         cudaFuncAttributeMaxDynamicSharedMemorySize, SMEM_C4_4);
    cudaFuncSetAttribute((const void*)conv_mma_kernel<4, 4, 2, 0>,
                         cudaFuncAttributeMaxDynamicSharedMemorySize, SMEM_C4_4);
    cudaFuncSetAttribute((const void*)conv_mma_kernel<1, 8, 1, 0>,
                         cudaFuncAttributeMaxDynamicSharedMemorySize, SMEM_C1_8);

    // ---- preconvert ALL weights in one launch ----
    wconv_all<<<(WSCRATCH2 + 255) / 256, 256>>>(w0, w1, w2, w3, w4, w5, w6, w7, WP);

    // ---- flow net ----
    // conv0: 3->32 @512 relu, staged directly from fp32 x   (x -> A)
    conv_mma_kernel<2, 8, 0, 1><<<dim3(8, 64, 4), 256, SMEM_C2_8>>>(
        nullptr, x, WP + 0, b0, Apk, nullptr, 512, 512, 1, 32);
    // conv1+pool: 32->32 @512 relu -> 256²  (A -> B)
    conv_mma_kernel<2, 8, 2, 0><<<dim3(8, 64, 4), 256, SMEM_C2_8>>>(
        Apk, nullptr, WP + 9216, b1, Bpk, nullptr, 512, 512, 2, 32);
    // conv2: 32->64 @256 relu         (B -> A)
    conv_mma_kernel<4, 4, 0, 0><<<dim3(8, 32, 4), 256, SMEM_C4_4>>>(
        Bpk, nullptr, WP + 27648, b2, Apk, nullptr, 256, 256, 2, 64);
    // conv3+pool: 64->64 @256 relu -> 128²  (A -> B)
    conv_mma_kernel<4, 4, 2, 0><<<dim3(8, 32, 4), 256, SMEM_C4_4>>>(
        Apk, nullptr, WP + 64512, b3, Bpk, nullptr, 256, 256, 4, 64);
    // up: 128->256                    (B -> A)
    {
        int total = BATCH * 4 * 256 * 256;
        up_bf16_v2<<<(total + 255) / 256, 256>>>(Bpk, Apk, total, 128, 128);
    }
    // conv4: 64->64 @256 relu         (A -> B)
    conv_mma_kernel<4, 4, 0, 0><<<dim3(8, 32, 4), 256, SMEM_C4_4>>>(
        Apk, nullptr, WP + 138240, b4, Bpk, nullptr, 256, 256, 4, 64);
    // conv5: 64->32 @256 relu         (B -> A)
    conv_mma_kernel<2, 8, 0, 0><<<dim3(4, 32, 4), 256, SMEM_C2_8>>>(
        Bpk, nullptr, WP + 211968, b5, Apk, nullptr, 256, 256, 4, 32);
    // up: 256->512                    (A -> B)
    {
        int total = BATCH * 2 * 512 * 512;
        up_bf16_v2<<<(total + 255) / 256, 256>>>(Apk, Bpk, total, 256, 256);
    }
    // conv6: 32->32 @512 relu         (B -> A)
    conv_mma_kernel<2, 8, 0, 0><<<dim3(8, 64, 4), 256, SMEM_C2_8>>>(
        Bpk, nullptr, WP + 248832, b6, Apk, nullptr, 512, 512, 2, 32);
    // conv7: 32->2 @512 tanh          (A -> flow, fp32)
    conv_mma_kernel<1, 8, 1, 0><<<dim3(8, 64, 4), 256, SMEM_C1_8>>>(
        Apk, nullptr, WP + 267264, b7, nullptr, flow, 512, 512, 2, 2);

    // deformed grid
    {
        int total = BATCH * IMG_H * IMG_W;
        deform_kernel<<<(total + 255) / 256, 256>>>(flow, temp, def);
    }
    // patches (512 threads: more latency hiding for the gather-heavy loop)
    patches_kernel<<<dim3(BATCH * NPATCH), 512>>>(x, def, patches);
}

// round 16
// speedup vs baseline: 1.4969x; 1.4969x over previous
#include <cuda_runtime.h>
#include <cuda_bf16.h>
#include <math.h>

// ---------------------------------------------------------------------------
// Problem constants
// ---------------------------------------------------------------------------
#define BATCH 4
#define IMG_H 512
#define IMG_W 512
#define PATCH 64
#define STRIDE_ 32
#define NPATCH 256
#define PATCHES_ELEMS (BATCH * NPATCH * 3 * PATCH * PATCH)   // 12,582,912
#define FLOW_ELEMS    (BATCH * 2 * IMG_H * IMG_W)            //  2,097,152

// Scratch (device globals). Activation = interleaved hi/lo, 32 bf16 per pixel.
__device__ __align__(256) float g_bufA[33554432];
__device__ __align__(256) float g_bufB[33554432];

// Packed weights: per (layer, cb, tap, ct): [32 lanes x 16B hi][32 lanes x 16B lo]
#define WSCRATCH2 276480
__device__ __align__(256) __nv_bfloat16 g_wpk[WSCRATCH2];

// ---------------------------------------------------------------------------
// helpers
// ---------------------------------------------------------------------------
__device__ __forceinline__ unsigned su32(const void* p) {
    return (unsigned)__cvta_generic_to_shared(p);
}
__device__ __forceinline__ void cp_async16(void* smem_dst, const void* gptr) {
    asm volatile("cp.async.cg.shared.global [%0], [%1], 16;"
                 :: "r"(su32(smem_dst)), "l"(gptr));
}
__device__ __forceinline__ void cp_commit() { asm volatile("cp.async.commit_group;"); }
__device__ __forceinline__ void cp_wait0()  { asm volatile("cp.async.wait_group 0;"); }

__device__ __forceinline__ void cp_bulk(unsigned sdst, const void* g, unsigned bytes,
                                        unsigned mbar) {
    asm volatile(
        "cp.async.bulk.shared::cta.global.mbarrier::complete_tx::bytes [%0], [%1], %2, [%3];"
        :: "r"(sdst), "l"(g), "r"(bytes), "r"(mbar) : "memory");
}
__device__ __forceinline__ void mbar_init(unsigned addr, unsigned cnt) {
    asm volatile("mbarrier.init.shared.b64 [%0], %1;" :: "r"(addr), "r"(cnt) : "memory");
}
__device__ __forceinline__ void mbar_expect_tx(unsigned addr, unsigned bytes) {
    asm volatile("mbarrier.arrive.expect_tx.shared.b64 _, [%0], %1;"
                 :: "r"(addr), "r"(bytes) : "memory");
}
__device__ __forceinline__ void mbar_wait(unsigned addr, unsigned parity) {
    asm volatile(
        "{\n\t.reg .pred P;\n\t"
        "W_%=:\n\t"
        "mbarrier.try_wait.parity.acquire.cta.shared::cta.b64 P, [%0], %1, 0x989680;\n\t"
        "@P bra.uni D_%=;\n\t"
        "bra.uni W_%=;\n\t"
        "D_%=:\n\t}"
        :: "r"(addr), "r"(parity) : "memory");
}

__device__ __forceinline__ void mma16816(float* c, const unsigned* a, unsigned b0, unsigned b1) {
    asm volatile(
        "mma.sync.aligned.m16n8k16.row.col.f32.bf16.bf16.f32 "
        "{%0,%1,%2,%3}, {%4,%5,%6,%7}, {%8,%9}, {%0,%1,%2,%3};"
        : "+f"(c[0]), "+f"(c[1]), "+f"(c[2]), "+f"(c[3])
        : "r"(a[0]), "r"(a[1]), "r"(a[2]), "r"(a[3]), "r"(b0), "r"(b1));
}

// slot permutation within 16 channels
__device__ __forceinline__ int pos16(int ci) {
    return (((ci >> 1) & 3) << 2) + (((ci >> 3) & 1) << 1) + (ci & 1);
}
// interleaved layout: hi offset = 8*(s>>2)+(s&3), lo = +4
__device__ __forceinline__ int hoff16(int s) { return 8 * (s >> 2) + (s & 3); }

__device__ __forceinline__ void bf16split(float v, __nv_bfloat16& h, __nv_bfloat16& l) {
    h = __float2bfloat16(v);
    l = __float2bfloat16(v - __bfloat162float(h));
}

// ---------------------------------------------------------------------------
// Fused weight preconversion: fp32 -> packed per-lane mma A-fragments.
// ---------------------------------------------------------------------------
__constant__ int c_woffs2[9] = {0, 9216, 27648, 64512, 138240, 211968, 248832, 267264, 276480};
__constant__ int c_wCOUT[8]  = {32, 32, 64, 64, 64, 32, 32, 2};
__constant__ int c_wCIN[8]   = {3, 32, 32, 64, 64, 64, 32, 32};
__constant__ int c_wNCT[8]   = {2, 2, 4, 4, 4, 2, 2, 1};

__global__ void wconv_all(const float* __restrict__ w0, const float* __restrict__ w1,
                          const float* __restrict__ w2, const float* __restrict__ w3,
                          const float* __restrict__ w4, const float* __restrict__ w5,
                          const float* __restrict__ w6, const float* __restrict__ w7,
                          __nv_bfloat16* __restrict__ dst)
{
    int idx = blockIdx.x * blockDim.x + threadIdx.x;
    if (idx >= WSCRATCH2) return;
    int l = 0;
    while (idx >= c_woffs2[l + 1]) l++;
    int rel = idx - c_woffs2[l];
    int COUT = c_wCOUT[l], CIN = c_wCIN[l], NCT = c_wNCT[l];
    int e    = rel & 255;
    int plane = (rel >> 8) & 1;
    int unit = rel >> 9;
    int ct  = unit % NCT;  unit /= NCT;
    int tap = unit % 9;
    int cb  = unit / 9;
    int lane = e >> 3;
    int e8 = e & 7;
    int j = e8 >> 1, kk = e8 & 1;
    int gid = lane >> 2, q = lane & 3;
    int co = ct * 16 + gid + (j & 1) * 8;
    int k  = 2 * q + kk + ((j & 2) ? 8 : 0);
    int ci_g = cb * 16 + k;
    const float* w;
    switch (l) {
        case 0: w = w0; break; case 1: w = w1; break;
        case 2: w = w2; break; case 3: w = w3; break;
        case 4: w = w4; break; case 5: w = w5; break;
        case 6: w = w6; break; default: w = w7; break;
    }
    float v = 0.f;
    if (co < COUT && ci_g < CIN)
        v = w[((size_t)co * CIN + ci_g) * 9 + tap];
    __nv_bfloat16 h = __float2bfloat16(v);
    dst[idx] = plane ? __float2bfloat16(v - __bfloat162float(h)) : h;
}

// ---------------------------------------------------------------------------
// Implicit-GEMM 3x3 conv via mma.sync bf16 (3-term hi/lo split), layout v2.
// Tile: (NT*8) wide x 8 tall x (NCT*16) couts. 256 threads (8 warps).
// Double-buffered input staging via cp.async.bulk + 3 mbarriers (INX=0);
// direct fp32->bf16 conversion from x (INX=1, conv0 only).
// OUTMODE: 0 = act layout (+relu); 1 = fp32 NCHW (+tanh) + fused deform;
//          2 = act layout, fused bias+relu+MaxPool2x2
// ---------------------------------------------------------------------------
template <int NCT, int NT, int OUTMODE, int INX>
__global__ void __launch_bounds__(256, 2)
conv_mma_kernel(const __nv_bfloat16* __restrict__ gact,
                const float* __restrict__ xin,
                const __nv_bfloat16* __restrict__ gw,
                const float* __restrict__ bias,
                __nv_bfloat16* __restrict__ oact,
                float* __restrict__ of32,
                float* __restrict__ odef,
                const float* __restrict__ temp,
                int H, int W, int CBIN, int COUT)
{
    constexpr int COUTP = NCT * 16;
    constexpr int TILEW = NT * 8;
    constexpr int PITCH = TILEW + 4;
    constexpr int INP = 10 * PITCH * 32;      // bf16 per input buffer
    constexpr int WPL = 9 * NCT * 512;        // bf16 per weight chunk
    extern __shared__ char smraw[];
    __nv_bfloat16* s_in0 = (__nv_bfloat16*)smraw;
    __nv_bfloat16* s_in1 = s_in0 + INP;
    __nv_bfloat16* s_w   = s_in0 + 2 * INP;
    const unsigned mb_base = su32(smraw) + (2 * INP + WPL) * 2;
    const unsigned mb_in0 = mb_base, mb_in1 = mb_base + 8, mb_w = mb_base + 16;

    const int bx = blockIdx.x * TILEW;
    const int by = blockIdx.y * 8;
    const int b  = blockIdx.z;

    const int tid  = threadIdx.x;
    const int warp = tid >> 5;
    const int lane = tid & 31;
    const int gid  = lane >> 2;
    const int qid  = lane & 3;

    float acc[NCT][NT][4];
#pragma unroll
    for (int ct = 0; ct < NCT; ct++)
#pragma unroll
        for (int nt = 0; nt < NT; nt++) {
            acc[ct][nt][0] = 0.f; acc[ct][nt][1] = 0.f;
            acc[ct][nt][2] = 0.f; acc[ct][nt][3] = 0.f;
        }

    // halo geometry (static per CTA)
    const int r0 = (by == 0) ? 1 : 0;
    const int r1 = (by + 8 >= H) ? 9 : 10;
    const int c0 = (bx == 0) ? 1 : 0;
    const int c1 = (bx + TILEW >= W) ? (TILEW + 1) : (TILEW + 2);
    const unsigned rowBytes = (unsigned)(c1 - c0) * 64u;
    const unsigned inBytes  = (unsigned)(r1 - r0) * rowBytes;

    if (!INX) {
        if (tid == 0) {
            mbar_init(mb_in0, 1);
            mbar_init(mb_in1, 1);
            mbar_init(mb_w, 1);
        }
        // zero-fill OOB halo ONCE in BOTH buffers
        for (int p = tid; p < 10 * (TILEW + 2); p += 256) {
            int row = p / (TILEW + 2);
            int col = p - row * (TILEW + 2);
            if (row < r0 || row >= r1 || col < c0 || col >= c1) {
                uint4 z = make_uint4(0u, 0u, 0u, 0u);
                uint4* d0 = (uint4*)(s_in0 + (row * PITCH + col) * 32);
                uint4* d1 = (uint4*)(s_in1 + (row * PITCH + col) * 32);
                d0[0] = z; d0[1] = z; d0[2] = z; d0[3] = z;
                d1[0] = z; d1[1] = z; d1[2] = z; d1[3] = z;
            }
        }
        __syncthreads();   // init + zero-fill visible before staging/waits
        if (tid == 0) {
            // prologue: input chunk 0 + weights chunk 0
            mbar_expect_tx(mb_in0, inBytes);
            for (int r = r0; r < r1; r++) {
                int gy = by + r - 1;
                const __nv_bfloat16* src = gact +
                    ((((size_t)b * CBIN + 0) * H + gy) * W + (bx + c0 - 1)) * 32;
                cp_bulk(su32(s_in0 + (r * PITCH + c0) * 32), src, rowBytes, mb_in0);
            }
            mbar_expect_tx(mb_w, (unsigned)WPL * 2u);
            cp_bulk(su32(s_w), gw, (unsigned)WPL * 2u, mb_w);
        }
    }

    int ph_in0 = 0, ph_in1 = 0, ph_w = 0;

    for (int cb = 0; cb < CBIN; cb++) {
        const int buf = cb & 1;
        if (INX) {
            __syncthreads();
            for (int idx = tid * 8; idx < WPL; idx += 2048)
                cp_async16(s_w + idx, gw + idx);
            for (int p = tid; p < 10 * (TILEW + 2); p += 256) {
                int row = p / (TILEW + 2);
                int col = p - row * (TILEW + 2);
                int gy = by + row - 1;
                int gx = bx + col - 1;
                __nv_bfloat16 arr[32];
#pragma unroll
                for (int i = 0; i < 32; i++) arr[i] = __float2bfloat16(0.f);
                if (gy >= 0 && gy < H && gx >= 0 && gx < W) {
#pragma unroll
                    for (int ci = 0; ci < 3; ci++) {
                        float v = xin[((size_t)(b * 3 + ci) * H + gy) * W + gx];
                        __nv_bfloat16 h, l;
                        bf16split(v, h, l);
                        int hf = hoff16(pos16(ci));
                        arr[hf] = h;
                        arr[hf + 4] = l;
                    }
                }
                uint4* src = (uint4*)arr;
                uint4* dst = (uint4*)(s_in0 + (row * PITCH + col) * 32);
                dst[0] = src[0]; dst[1] = src[1]; dst[2] = src[2]; dst[3] = src[3];
            }
            cp_commit();
            cp_wait0();
            __syncthreads();
        } else {
            // issue input prefetch for chunk cb+1 into the other buffer
            if (tid == 0 && cb + 1 < CBIN) {
                unsigned mb_n = buf ? mb_in0 : mb_in1;
                __nv_bfloat16* s_n = buf ? s_in0 : s_in1;
                mbar_expect_tx(mb_n, inBytes);
                for (int r = r0; r < r1; r++) {
                    int gy = by + r - 1;
                    const __nv_bfloat16* src = gact +
                        ((((size_t)b * CBIN + (cb + 1)) * H + gy) * W + (bx + c0 - 1)) * 32;
                    cp_bulk(su32(s_n + (r * PITCH + c0) * 32), src, rowBytes, mb_n);
                }
            }
            // wait current input + weights
            if (buf == 0) { mbar_wait(mb_in0, (unsigned)ph_in0); ph_in0 ^= 1; }
            else          { mbar_wait(mb_in1, (unsigned)ph_in1); ph_in1 ^= 1; }
            mbar_wait(mb_w, (unsigned)ph_w); ph_w ^= 1;
        }

        const __nv_bfloat16* s_act = buf ? s_in1 : s_in0;

        // ---- compute: 9 taps ----
        int ky = 0, kx = 0;
#pragma unroll 1
        for (int tap = 0; tap < 9; tap++) {
            unsigned ah[NCT][4], al[NCT][4];
            const int wb = tap * NCT * 512 + lane * 8;
#pragma unroll
            for (int ct = 0; ct < NCT; ct++) {
                uint4 hv = *(const uint4*)(s_w + wb + ct * 512);
                uint4 lv = *(const uint4*)(s_w + wb + ct * 512 + 256);
                ah[ct][0] = hv.x; ah[ct][1] = hv.y; ah[ct][2] = hv.z; ah[ct][3] = hv.w;
                al[ct][0] = lv.x; al[ct][1] = lv.y; al[ct][2] = lv.z; al[ct][3] = lv.w;
            }
            const int rowb = warp + ky;
#pragma unroll
            for (int nt = 0; nt < NT; nt++) {
                int colb = nt * 8 + gid + kx;
                uint4 bv = *(const uint4*)(s_act + (rowb * PITCH + colb) * 32 + 8 * qid);
#pragma unroll
                for (int ct = 0; ct < NCT; ct++) {
                    mma16816(acc[ct][nt], ah[ct], bv.x, bv.y);
                    mma16816(acc[ct][nt], ah[ct], bv.z, bv.w);
                    mma16816(acc[ct][nt], al[ct], bv.x, bv.y);
                }
            }
            if (++kx == 3) { kx = 0; ++ky; }
        }

        if (!INX && cb + 1 < CBIN) {
            __syncthreads();   // all warps done with s_w before overwrite
            if (tid == 0) {
                mbar_expect_tx(mb_w, (unsigned)WPL * 2u);
                cp_bulk(su32(s_w), gw + (size_t)(cb + 1) * WPL, (unsigned)WPL * 2u, mb_w);
            }
        }
    }

    // ---- epilogue ----
    const int gy = by + warp;
    if (OUTMODE == 1) {
        // fp32 NCHW flow (+tanh), plus fused deform:
        // def[b][gy][gx][co] = base(co) + v * temp
        const float t = temp[0];
        const float byy = -1.0f + 2.0f * (float)gy / (float)(H - 1);
#pragma unroll
        for (int ct = 0; ct < NCT; ct++) {
            int co0r = ct * 16 + gid;
            int co1r = co0r + 8;
            bool ok0 = co0r < COUT;
            bool ok1 = co1r < COUT;
            float bv0 = ok0 ? bias[co0r] : 0.f;
            float bv1 = ok1 ? bias[co1r] : 0.f;
#pragma unroll
            for (int nt = 0; nt < NT; nt++) {
                int gxv = bx + nt * 8 + 2 * qid;
                if (ok0) {
                    float v0 = tanhf(acc[ct][nt][0] + bv0);
                    float v1 = tanhf(acc[ct][nt][1] + bv0);
                    *(float2*)&of32[((size_t)(b * COUT + co0r) * H + gy) * W + gxv]
                        = make_float2(v0, v1);
                    float base0 = (co0r == 0)
                        ? (-1.0f + 2.0f * (float)gxv / (float)(W - 1)) : byy;
                    float base1 = (co0r == 0)
                        ? (-1.0f + 2.0f * (float)(gxv + 1) / (float)(W - 1)) : byy;
                    size_t d = (((size_t)b * H + gy) * W + gxv) * 2 + co0r;
                    odef[d]     = base0 + v0 * t;
                    odef[d + 2] = base1 + v1 * t;
                }
                if (ok1) {
                    float v0 = tanhf(acc[ct][nt][2] + bv1);
                    float v1 = tanhf(acc[ct][nt][3] + bv1);
                    *(float2*)&of32[((size_t)(b * COUT + co1r) * H + gy) * W + gxv]
                        = make_float2(v0, v1);
                }
            }
        }
    } else if (OUTMODE == 0) {
        const int nCBo = COUT >> 4;
        const int s0 = 4 * (gid >> 1) + (gid & 1);
        const int hf0 = hoff16(s0);
        const int hf1 = hf0 + 2;
#pragma unroll
        for (int ct = 0; ct < NCT; ct++) {
            int co_g = ct * 16 + gid;
            int cbo = co_g >> 4;
            float bv0 = bias[co_g];
            float bv1 = bias[co_g + 8];
#pragma unroll
            for (int nt = 0; nt < NT; nt++) {
                int gxv = bx + nt * 8 + 2 * qid;
                size_t g = ((((size_t)b * nCBo + cbo) * H + gy) * W + gxv) * 32;
                float v0 = fmaxf(acc[ct][nt][0] + bv0, 0.f);
                float v1 = fmaxf(acc[ct][nt][1] + bv0, 0.f);
                float v2 = fmaxf(acc[ct][nt][2] + bv1, 0.f);
                float v3 = fmaxf(acc[ct][nt][3] + bv1, 0.f);
                __nv_bfloat16 h, l;
                bf16split(v0, h, l); oact[g + hf0]          = h; oact[g + hf0 + 4]      = l;
                bf16split(v1, h, l); oact[g + 32 + hf0]     = h; oact[g + 32 + hf0 + 4] = l;
                bf16split(v2, h, l); oact[g + hf1]          = h; oact[g + hf1 + 4]      = l;
                bf16split(v3, h, l); oact[g + 32 + hf1]     = h; oact[g + 32 + hf1 + 4] = l;
            }
        }
    } else {
        // OUTMODE 2: fused bias + relu + MaxPool 2x2
        constexpr int PW = NT * 4;
        constexpr int PC = COUTP + 1;
        float* s_pool = (float*)smraw;
        __syncthreads();
#pragma unroll
        for (int ct = 0; ct < NCT; ct++) {
            float bv0 = bias[ct * 16 + gid];
            float bv1 = bias[ct * 16 + 8 + gid];
#pragma unroll
            for (int nt = 0; nt < NT; nt++) {
                float v0 = fmaxf(acc[ct][nt][0] + bv0, 0.f);
                float v1 = fmaxf(acc[ct][nt][1] + bv0, 0.f);
                float v2 = fmaxf(acc[ct][nt][2] + bv1, 0.f);
                float v3 = fmaxf(acc[ct][nt][3] + bv1, 0.f);
                int px = nt * 4 + qid;
                s_pool[(warp * PW + px) * PC + ct * 16 + gid]     = fmaxf(v0, v1);
                s_pool[(warp * PW + px) * PC + ct * 16 + 8 + gid] = fmaxf(v2, v3);
            }
        }
        __syncthreads();
        const int H2 = H >> 1, W2 = W >> 1;
        const int nCBo = COUT >> 4;
        constexpr int TOTP = 4 * PW * COUTP;
        for (int v = tid; v < TOTP; v += 256) {
            int co = v & (COUTP - 1);
            int rest = v >> (NCT == 4 ? 6 : 5);
            int px = rest & (PW - 1);
            int prow = rest / PW;
            float a = s_pool[((2 * prow) * PW + px) * PC + co];
            float bq = s_pool[((2 * prow + 1) * PW + px) * PC + co];
            float m = fmaxf(a, bq);
            int gy2 = (by >> 1) + prow;
            int gx2 = (bx >> 1) + px;
            int cbo = co >> 4;
            int hf = hoff16(pos16(co & 15));
            size_t g = ((((size_t)b * nCBo + cbo) * H2 + gy2) * W2 + gx2) * 32;
            __nv_bfloat16 h, l;
            bf16split(m, h, l);
            oact[g + hf] = h;
            oact[g + hf + 4] = l;
        }
    }
}

// ---------------------------------------------------------------------------
// Bilinear upsample x2, vectorized: 1 thread per output pixel (32 bf16).
// ---------------------------------------------------------------------------
__global__ void up_bf16_v2(const __nv_bfloat16* __restrict__ iact,
                           __nv_bfloat16* __restrict__ oact,
                           int total, int Hin, int Win)
{
    int p = blockIdx.x * blockDim.x + threadIdx.x;
    if (p >= total) return;
    int Hout = 2 * Hin, Wout = 2 * Win;
    int ox = p % Wout;
    int t = p / Wout;
    int oy = t % Hout;
    int c = t / Hout;

    float fy = (oy + 0.5f) * 0.5f - 0.5f;
    float fx = (ox + 0.5f) * 0.5f - 0.5f;
    int y0 = (int)floorf(fy);
    int x0 = (int)floorf(fx);
    float wy = fy - (float)y0;
    float wx = fx - (float)x0;
    int y0c = max(y0, 0), y1c = min(y0 + 1, Hin - 1);
    int x0c = max(x0, 0), x1c = min(x0 + 1, Win - 1);
    float w00 = (1.f - wy) * (1.f - wx), w01 = (1.f - wy) * wx;
    float w10 = wy * (1.f - wx),         w11 = wy * wx;

    size_t cb = (size_t)c * Hin;
    const uint4* p00 = (const uint4*)(iact + ((cb + y0c) * Win + x0c) * 32);
    const uint4* p01 = (const uint4*)(iact + ((cb + y0c) * Win + x1c) * 32);
    const uint4* p10 = (const uint4*)(iact + ((cb + y1c) * Win + x0c) * 32);
    const uint4* p11 = (const uint4*)(iact + ((cb + y1c) * Win + x1c) * 32);

    __nv_bfloat16 a00[32], a01[32], a10[32], a11[32], o[32];
#pragma unroll
    for (int i = 0; i < 4; i++) {
        ((uint4*)a00)[i] = p00[i];
        ((uint4*)a01)[i] = p01[i];
        ((uint4*)a10)[i] = p10[i];
        ((uint4*)a11)[i] = p11[i];
    }
#pragma unroll
    for (int g = 0; g < 4; g++) {
#pragma unroll
        for (int k = 0; k < 4; k++) {
            int hi = 8 * g + k, lo = hi + 4;
            float v00 = __bfloat162float(a00[hi]) + __bfloat162float(a00[lo]);
            float v01 = __bfloat162float(a01[hi]) + __bfloat162float(a01[lo]);
            float v10 = __bfloat162float(a10[hi]) + __bfloat162float(a10[lo]);
            float v11 = __bfloat162float(a11[hi]) + __bfloat162float(a11[lo]);
            float v = w00 * v00 + w01 * v01 + w10 * v10 + w11 * v11;
            __nv_bfloat16 h, l;
            bf16split(v, h, l);
            o[hi] = h;
            o[lo] = l;
        }
    }
    uint4* dst = (uint4*)(oact + (size_t)p * 32);
#pragma unroll
    for (int i = 0; i < 4; i++) dst[i] = ((uint4*)o)[i];
}

// ---------------------------------------------------------------------------
// Patch extraction (grid_sample bilinear, zeros padding)
// ---------------------------------------------------------------------------
__global__ void patches_kernel(const float* __restrict__ x,
                               const float* __restrict__ def,
                               float* __restrict__ out)
{
    int bn = blockIdx.x;
    int b = bn >> 8;
    int n = bn & 255;
    int hy = n >> 4;
    int wx = n & 15;
    const float* dptr = def + (((size_t)(b * IMG_H + hy * STRIDE_) * IMG_W) + wx * STRIDE_) * 2;
    float cx = dptr[0];
    float cy = dptr[1];

    for (int p = threadIdx.x; p < PATCH * PATCH; p += blockDim.x) {
        int i = p >> 6;
        int j = p & 63;
        float pxv = -1.0f + 2.0f * (float)j / (float)(PATCH - 1);
        float pyv = -1.0f + 2.0f * (float)i / (float)(PATCH - 1);
        float gx = cx + pxv * ((float)PATCH / (float)IMG_W);
        float gy = cy + pyv * ((float)PATCH / (float)IMG_H);
        float ix = ((gx + 1.0f) * (float)IMG_W - 1.0f) * 0.5f;
        float iy = ((gy + 1.0f) * (float)IMG_H - 1.0f) * 0.5f;
        float x0f = floorf(ix), y0f = floorf(iy);
        float wx1 = ix - x0f, wy1 = iy - y0f;
        int x0 = (int)x0f, y0 = (int)y0f;
        int x1 = x0 + 1, y1 = y0 + 1;
        bool vx0 = (x0 >= 0) & (x0 <= IMG_W - 1);
        bool vx1 = (x1 >= 0) & (x1 <= IMG_W - 1);
        bool vy0 = (y0 >= 0) & (y0 <= IMG_H - 1);
        bool vy1 = (y1 >= 0) & (y1 <= IMG_H - 1);
        int x0c = min(max(x0, 0), IMG_W - 1);
        int x1c = min(max(x1, 0), IMG_W - 1);
        int y0c = min(max(y0, 0), IMG_H - 1);
        int y1c = min(max(y1, 0), IMG_H - 1);
        float w00 = (1.f - wx1) * (1.f - wy1) * (float)(vx0 && vy0);
        float w10 = wx1 * (1.f - wy1) * (float)(vx1 && vy0);
        float w01 = (1.f - wx1) * wy1 * (float)(vx0 && vy1);
        float w11 = wx1 * wy1 * (float)(vx1 && vy1);

#pragma unroll
        for (int c = 0; c < 3; c++) {
            const float* img = x + (size_t)(b * 3 + c) * IMG_H * IMG_W;
            float v = img[y0c * IMG_W + x0c] * w00
                    + img[y0c * IMG_W + x1c] * w10
                    + img[y1c * IMG_W + x0c] * w01
                    + img[y1c * IMG_W + x1c] * w11;
            out[((size_t)(bn)*3 + c) * (PATCH * PATCH) + p] = v;
        }
    }
}

// ---------------------------------------------------------------------------
// Launch
// ---------------------------------------------------------------------------
#define SMEM_C2_8 ((2 * 10 * 68 * 32 + 9 * 2 * 512) * 2 + 32)   // 105,504 B
#define SMEM_C4_4 ((2 * 10 * 36 * 32 + 9 * 4 * 512) * 2 + 32)   //  82,976 B
#define SMEM_C1_8 ((2 * 10 * 68 * 32 + 9 * 1 * 512) * 2 + 32)   //  96,288 B

extern "C" void kernel_launch(void* const* d_in, const int* in_sizes, int n_in,
                              void* d_out, int out_size)
{
    const float* x  = (const float*)d_in[0];
    const float* w0 = (const float*)d_in[1];  const float* b0 = (const float*)d_in[2];
    const float* w1 = (const float*)d_in[3];  const float* b1 = (const float*)d_in[4];
    const float* w2 = (const float*)d_in[5];  const float* b2 = (const float*)d_in[6];
    const float* w3 = (const float*)d_in[7];  const float* b3 = (const float*)d_in[8];
    const float* w4 = (const float*)d_in[9];  const float* b4 = (const float*)d_in[10];
    const float* w5 = (const float*)d_in[11]; const float* b5 = (const float*)d_in[12];
    const float* w6 = (const float*)d_in[13]; const float* b6 = (const float*)d_in[14];
    const float* w7 = (const float*)d_in[15]; const float* b7 = (const float*)d_in[16];
    const float* temp = (const float*)d_in[17];

    float* out     = (float*)d_out;
    float* patches = out;
    float* flow    = out + PATCHES_ELEMS;
    float* def     = out + PATCHES_ELEMS + FLOW_ELEMS;

    float* A;  cudaGetSymbolAddress((void**)&A, g_bufA);
    float* Bb; cudaGetSymbolAddress((void**)&Bb, g_bufB);
    __nv_bfloat16* WP; cudaGetSymbolAddress((void**)&WP, g_wpk);

    __nv_bfloat16* Apk = (__nv_bfloat16*)A;
    __nv_bfloat16* Bpk = (__nv_bfloat16*)Bb;

    cudaFuncSetAttribute((const void*)conv_mma_kernel<2, 8, 0, 1>,
                         cudaFuncAttributeMaxDynamicSharedMemorySize, SMEM_C2_8);
    cudaFuncSetAttribute((const void*)conv_mma_kernel<2, 8, 0, 0>,
                         cudaFuncAttributeMaxDynamicSharedMemorySize, SMEM_C2_8);
    cudaFuncSetAttribute((const void*)conv_mma_kernel<2, 8, 2, 0>,
                         cudaFuncAttributeMaxDynamicSharedMemorySize, SMEM_C2_8);
    cudaFuncSetAttribute((const void*)conv_mma_kernel<4, 4, 0, 0>,
                         cudaFuncAttributeMaxDynamicSharedMemorySize, SMEM_C4_4);
    cudaFuncSetAttribute((const void*)conv_mma_kernel<4, 4, 2, 0>,
                         cudaFuncAttributeMaxDynamicSharedMemorySize, SMEM_C4_4);
    cudaFuncSetAttribute((const void*)conv_mma_kernel<1, 8, 1, 0>,
                         cudaFuncAttributeMaxDynamicSharedMemorySize, SMEM_C1_8);

    // ---- preconvert ALL weights in one launch ----
    wconv_all<<<(WSCRATCH2 + 255) / 256, 256>>>(w0, w1, w2, w3, w4, w5, w6, w7, WP);

    // ---- flow net ----
    // conv0: 3->32 @512 relu, staged directly from fp32 x   (x -> A)
    conv_mma_kernel<2, 8, 0, 1><<<dim3(8, 64, 4), 256, SMEM_C2_8>>>(
        nullptr, x, WP + 0, b0, Apk, nullptr, nullptr, nullptr, 512, 512, 1, 32);
    // conv1+pool: 32->32 @512 relu -> 256²  (A -> B)
    conv_mma_kernel<2, 8, 2, 0><<<dim3(8, 64, 4), 256, SMEM_C2_8>>>(
        Apk, nullptr, WP + 9216, b1, Bpk, nullptr, nullptr, nullptr, 512, 512, 2, 32);
    // conv2: 32->64 @256 relu         (B -> A)
    conv_mma_kernel<4, 4, 0, 0><<<dim3(8, 32, 4), 256, SMEM_C4_4>>>(
        Bpk, nullptr, WP + 27648, b2, Apk, nullptr, nullptr, nullptr, 256, 256, 2, 64);
    // conv3+pool: 64->64 @256 relu -> 128²  (A -> B)
    conv_mma_kernel<4, 4, 2, 0><<<dim3(8, 32, 4), 256, SMEM_C4_4>>>(
        Apk, nullptr, WP + 64512, b3, Bpk, nullptr, nullptr, nullptr, 256, 256, 4, 64);
    // up: 128->256                    (B -> A)
    {
        int total = BATCH * 4 * 256 * 256;
        up_bf16_v2<<<(total + 255) / 256, 256>>>(Bpk, Apk, total, 128, 128);
    }
    // conv4: 64->64 @256 relu         (A -> B)
    conv_mma_kernel<4, 4, 0, 0><<<dim3(8, 32, 4), 256, SMEM_C4_4>>>(
        Apk, nullptr, WP + 138240, b4, Bpk, nullptr, nullptr, nullptr, 256, 256, 4, 64);
    // conv5: 64->32 @256 relu         (B -> A)
    conv_mma_kernel<2, 8, 0, 0><<<dim3(4, 32, 4), 256, SMEM_C2_8>>>(
        Bpk, nullptr, WP + 211968, b5, Apk, nullptr, nullptr, nullptr, 256, 256, 4, 32);
    // up: 256->512                    (A -> B)
    {
        int total = BATCH * 2 * 512 * 512;
        up_bf16_v2<<<(total + 255) / 256, 256>>>(Apk, Bpk, total, 256, 256);
    }
    // conv6: 32->32 @512 relu         (B -> A)
    conv_mma_kernel<2, 8, 0, 0><<<dim3(8, 64, 4), 256, SMEM_C2_8>>>(
        Bpk, nullptr, WP + 248832, b6, Apk, nullptr, nullptr, nullptr, 512, 512, 2, 32);
    // conv7: 32->2 @512 tanh + fused deform  (A -> flow, def)
    conv_mma_kernel<1, 8, 1, 0><<<dim3(8, 64, 4), 256, SMEM_C1_8>>>(
        Apk, nullptr, WP + 267264, b7, nullptr, flow, def, temp, 512, 512, 2, 2);

    // patches
    patches_kernel<<<dim3(BATCH * NPATCH), 256>>>(x, def, patches);
}